// round 9
// baseline (speedup 1.0000x reference)
#include <cuda_runtime.h>
#include <cuda_fp16.h>
#include <cstring>

#define B_    2
#define C_    32
#define H_    128
#define W_    256
#define MAXD  12
#define D_    23            // 2*MAXD - 1
#define HW    (H_ * W_)
#define WT    256           // 2 split-groups x 128 pixels
#define NPIX  128           // pixels per CTA (half row)
#define NG    8             // channel quads: (2g, 2g+1, 2g+16, 2g+17)
#define SW2   220           // window: 76 left halo + 128 + 16 right
#define HALO  76
#define DG    12            // disparities per split (d=11 computed by both)
#define TAPS  13            // DG + 1

__device__ __forceinline__ __half2 u2h2(unsigned u) {
    __half2 r; memcpy(&r, &u, 4); return r;
}

// out[b,d,h,w] = sum_c |feat_l[b,c,h,w] - (w0*fr[c,x0+d] + w1*fr[c,x0+d+1])|
// R6 data path (fp16 4-channel quads, 13 x LDS.64 gather per quad, half2
// accum / fp32 flush) with the two d-splits FUSED into one 256-thread CTA:
// threads 0-127 compute dlo=0, threads 128-255 compute dlo=11 for the same
// half-row, sharing ONE window fill (R6 built it twice). Fill stays scalar
// LDG.32 + STS.64 (R8 showed the vectorized variant costs more wavefronts).
__global__ __launch_bounds__(WT)
void cost_volume_kernel(const float* __restrict__ feat_l,
                        const float* __restrict__ feat_r,
                        const float* __restrict__ disp,
                        float* __restrict__ out)
{
    __shared__ __align__(16) uint2 s_q[NG][SW2];   // 14080 B

    const int half_ = blockIdx.x;        // 0 or 1
    const int h     = blockIdx.y;
    const int b     = blockIdx.z;
    const int tid   = threadIdx.x;
    const int pix   = tid & (NPIX - 1);  // 0..127
    const int grp   = tid >> 7;          // 0 or 1
    const int W0    = half_ * NPIX;
    const int base  = W0 - HALO;         // global x of window index 0
    const int dlo   = grp * 11;          // 0 or 11

    // ---- stage zero-padded feat_r window (one position per thread) ----
    {
        const float* fr0 = feat_r + (((long)b * C_) * H_ + h) * W_;
        const int i = tid;
        if (i < SW2) {
            const int gx = base + i;
            const bool v = (gx >= 0) & (gx < W_);
            const int gxc = v ? gx : 0;
            #pragma unroll
            for (int g = 0; g < NG; g++) {
                const float c0  = v ? __ldg(fr0 + (2*g)      * HW + gxc) : 0.0f;
                const float c1  = v ? __ldg(fr0 + (2*g + 1)  * HW + gxc) : 0.0f;
                const float c16 = v ? __ldg(fr0 + (2*g + 16) * HW + gxc) : 0.0f;
                const float c17 = v ? __ldg(fr0 + (2*g + 17) * HW + gxc) : 0.0f;
                __half2 p = __floats2half2_rn(c0, c16);
                __half2 q = __floats2half2_rn(c1, c17);
                uint2 o;
                memcpy(&o.x, &p, 4); memcpy(&o.y, &q, 4);
                s_q[g][i] = o;
            }
        }
    }

    // ---- per-thread interpolation setup (overlaps fill) ----
    const int   w    = W0 + pix;
    const float dval = __ldg(disp + ((long)b * H_ + h) * W_ + w);
    const float px0  = ((float)w - dval) - (float)(MAXD - 1);
    const float xf   = floorf(px0);
    const float w1   = px0 - xf;          // right-neighbor weight (const over d)
    const float w0   = 1.0f - w1;
    int x0l = (int)xf - base;             // in [pix+1, pix+65]
    x0l = max(0, min(SW2 - 24, x0l));     // xs + TAPS <= 220 for both groups
    const int xs = x0l + dlo;

    const __half2 nw0 = __float2half2_rn(-w0);
    const __half2 nw1 = __float2half2_rn(-w1);

    // ---- hoist all 32 feat_l values into 16 half2 regs (pure LDG, no smem) ----
    __half2 flc[NG][2];
    {
        const float* fl0 = feat_l + (((long)b * C_) * H_ + h) * W_ + w;
        #pragma unroll
        for (int g = 0; g < NG; g++) {
            const float fa  = __ldg(fl0 + (2*g)      * HW);
            const float fb  = __ldg(fl0 + (2*g + 1)  * HW);
            const float fa2 = __ldg(fl0 + (2*g + 16) * HW);
            const float fb2 = __ldg(fl0 + (2*g + 17) * HW);
            flc[g][0] = __floats2half2_rn(fa, fa2);
            flc[g][1] = __floats2half2_rn(fb, fb2);
        }
    }

    __syncthreads();

    float accf[DG];
    #pragma unroll
    for (int d = 0; d < DG; d++) accf[d] = 0.0f;

    #pragma unroll 1
    for (int gg = 0; gg < NG / 2; gg++) {          // 4 outer groups (8 channels)
        __half2 acc2[DG];
        #pragma unroll
        for (int d = 0; d < DG; d++) acc2[d] = __float2half2_rn(0.0f);

        #pragma unroll
        for (int sub = 0; sub < 2; sub++) {
            const int g = gg * 2 + sub;
            const uint2* row = &s_q[g][xs];
            uint2 t[TAPS];
            #pragma unroll
            for (int j = 0; j < TAPS; j++) t[j] = row[j];   // 13 x LDS.64

            const __half2 fA = flc[g][0];
            const __half2 fB = flc[g][1];
            #pragma unroll
            for (int d = 0; d < DG; d++) {
                __half2 u0 = __hfma2(u2h2(t[d].x),     nw0, fA);
                u0         = __hfma2(u2h2(t[d + 1].x), nw1, u0);
                __half2 u1 = __hfma2(u2h2(t[d].y),     nw0, fB);
                u1         = __hfma2(u2h2(t[d + 1].y), nw1, u1);
                acc2[d] = __hadd2(acc2[d], __hadd2(__habs2(u0), __habs2(u1)));
            }
        }

        // flush packed half accumulators to fp32
        #pragma unroll
        for (int d = 0; d < DG; d++) {
            float2 f = __half22float2(acc2[d]);
            accf[d] += f.x + f.y;
        }
    }

    // ---- write out[b, dlo+d, h, w] (d=11 written by both groups, same value) ----
    float* orow = out + (((long)b * D_ + dlo) * H_ + h) * W_ + w;
    #pragma unroll
    for (int d = 0; d < DG; d++)
        orow[(long)d * HW] = accf[d];
}

extern "C" void kernel_launch(void* const* d_in, const int* in_sizes, int n_in,
                              void* d_out, int out_size)
{
    (void)in_sizes; (void)n_in; (void)out_size;
    const float* feat_l = (const float*)d_in[0];
    const float* feat_r = (const float*)d_in[1];
    const float* disp   = (const float*)d_in[2];
    float* out = (float*)d_out;

    dim3 grid(2, H_, B_);     // 512 CTAs x 8 warps (both d-splits per CTA)
    cost_volume_kernel<<<grid, WT>>>(feat_l, feat_r, disp, out);
}

// round 10
// speedup vs baseline: 1.0019x; 1.0019x over previous
#include <cuda_runtime.h>
#include <cuda_fp16.h>
#include <cstring>

#define B_    2
#define C_    32
#define H_    128
#define W_    256
#define MAXD  12
#define D_    23            // 2*MAXD - 1
#define HW    (H_ * W_)
#define WT    256           // 2 split-groups x 128 pixels
#define NPIX  128           // pixels per CTA (half row)
#define NG    8             // channel quads: (2g, 2g+1, 2g+16, 2g+17)
#define SW2   220           // window: 76 left halo + 128 + 16 right
#define HALO  76
#define DG    12            // disparities per split (d=11 computed by both)
#define TAPS  13            // DG + 1

__device__ __forceinline__ __half2 u2h2(unsigned u) {
    __half2 r; memcpy(&r, &u, 4); return r;
}

// out[b,d,h,w] = sum_c |feat_l[b,c,h,w] - (w0*fr[c,x0+d] + w1*fr[c,x0+d+1])|
// R6 data path (fp16 4-channel quads, 13 x LDS.64 gather per quad, in-loop
// feat_l loads, half2 accum / fp32 flush) with the two d-splits FUSED into
// one 256-thread CTA sharing ONE window fill. The feat_l hoist that R8/R9
// both carried (and that caused their identical +1.7us regression via
// front-batched LDG queue contention) is reverted: feat_l is loaded in-loop,
// spaced through the mainloop, exactly as in the 15.1us champion.
__global__ __launch_bounds__(WT)
void cost_volume_kernel(const float* __restrict__ feat_l,
                        const float* __restrict__ feat_r,
                        const float* __restrict__ disp,
                        float* __restrict__ out)
{
    __shared__ __align__(16) uint2 s_q[NG][SW2];   // 14080 B

    const int half_ = blockIdx.x;        // 0 or 1
    const int h     = blockIdx.y;
    const int b     = blockIdx.z;
    const int tid   = threadIdx.x;
    const int pix   = tid & (NPIX - 1);  // 0..127
    const int grp   = tid >> 7;          // 0 or 1
    const int W0    = half_ * NPIX;
    const int base  = W0 - HALO;         // global x of window index 0
    const int dlo   = grp * 11;          // 0 or 11

    // ---- stage zero-padded feat_r window (one position per thread) ----
    {
        const float* fr0 = feat_r + (((long)b * C_) * H_ + h) * W_;
        const int i = tid;
        if (i < SW2) {
            const int gx = base + i;
            const bool v = (gx >= 0) & (gx < W_);
            const int gxc = v ? gx : 0;
            #pragma unroll
            for (int g = 0; g < NG; g++) {
                const float c0  = v ? __ldg(fr0 + (2*g)      * HW + gxc) : 0.0f;
                const float c1  = v ? __ldg(fr0 + (2*g + 1)  * HW + gxc) : 0.0f;
                const float c16 = v ? __ldg(fr0 + (2*g + 16) * HW + gxc) : 0.0f;
                const float c17 = v ? __ldg(fr0 + (2*g + 17) * HW + gxc) : 0.0f;
                __half2 p = __floats2half2_rn(c0, c16);
                __half2 q = __floats2half2_rn(c1, c17);
                uint2 o;
                memcpy(&o.x, &p, 4); memcpy(&o.y, &q, 4);
                s_q[g][i] = o;
            }
        }
    }

    // ---- per-thread interpolation setup (overlaps fill) ----
    const int   w    = W0 + pix;
    const float dval = __ldg(disp + ((long)b * H_ + h) * W_ + w);
    const float px0  = ((float)w - dval) - (float)(MAXD - 1);
    const float xf   = floorf(px0);
    const float w1   = px0 - xf;          // right-neighbor weight (const over d)
    const float w0   = 1.0f - w1;
    int x0l = (int)xf - base;             // in [pix+1, pix+65]
    x0l = max(0, min(SW2 - 24, x0l));     // xs + TAPS <= 220 for both groups
    const int xs = x0l + dlo;

    const __half2 nw0 = __float2half2_rn(-w0);
    const __half2 nw1 = __float2half2_rn(-w1);

    __syncthreads();

    float accf[DG];
    #pragma unroll
    for (int d = 0; d < DG; d++) accf[d] = 0.0f;

    const float* fl0 = feat_l + (((long)b * C_) * H_ + h) * W_ + w;

    #pragma unroll 1
    for (int gg = 0; gg < NG / 2; gg++) {          // 4 outer groups (8 channels)
        __half2 acc2[DG];
        #pragma unroll
        for (int d = 0; d < DG; d++) acc2[d] = __float2half2_rn(0.0f);

        #pragma unroll
        for (int sub = 0; sub < 2; sub++) {
            const int g = gg * 2 + sub;
            // in-loop feat_l loads (spaced, overlap with FMA of prior steps)
            const float fa  = __ldg(fl0 + (2*g)      * HW);
            const float fb  = __ldg(fl0 + (2*g + 1)  * HW);
            const float fa2 = __ldg(fl0 + (2*g + 16) * HW);
            const float fb2 = __ldg(fl0 + (2*g + 17) * HW);
            const __half2 fA = __floats2half2_rn(fa, fa2);
            const __half2 fB = __floats2half2_rn(fb, fb2);

            const uint2* row = &s_q[g][xs];
            uint2 t[TAPS];
            #pragma unroll
            for (int j = 0; j < TAPS; j++) t[j] = row[j];   // 13 x LDS.64

            #pragma unroll
            for (int d = 0; d < DG; d++) {
                __half2 u0 = __hfma2(u2h2(t[d].x),     nw0, fA);
                u0         = __hfma2(u2h2(t[d + 1].x), nw1, u0);
                __half2 u1 = __hfma2(u2h2(t[d].y),     nw0, fB);
                u1         = __hfma2(u2h2(t[d + 1].y), nw1, u1);
                acc2[d] = __hadd2(acc2[d], __hadd2(__habs2(u0), __habs2(u1)));
            }
        }

        // flush packed half accumulators to fp32
        #pragma unroll
        for (int d = 0; d < DG; d++) {
            float2 f = __half22float2(acc2[d]);
            accf[d] += f.x + f.y;
        }
    }

    // ---- write out[b, dlo+d, h, w] (d=11 written by both groups, same value) ----
    float* orow = out + (((long)b * D_ + dlo) * H_ + h) * W_ + w;
    #pragma unroll
    for (int d = 0; d < DG; d++)
        orow[(long)d * HW] = accf[d];
}

extern "C" void kernel_launch(void* const* d_in, const int* in_sizes, int n_in,
                              void* d_out, int out_size)
{
    (void)in_sizes; (void)n_in; (void)out_size;
    const float* feat_l = (const float*)d_in[0];
    const float* feat_r = (const float*)d_in[1];
    const float* disp   = (const float*)d_in[2];
    float* out = (float*)d_out;

    dim3 grid(2, H_, B_);     // 512 CTAs x 8 warps (both d-splits per CTA)
    cost_volume_kernel<<<grid, WT>>>(feat_l, feat_r, disp, out);
}

// round 11
// speedup vs baseline: 1.1407x; 1.1385x over previous
#include <cuda_runtime.h>
#include <cuda_fp16.h>
#include <cstring>

#define B_    2
#define C_    32
#define H_    128
#define W_    256
#define MAXD  12
#define D_    23            // 2*MAXD - 1
#define HW    (H_ * W_)
#define WT    128           // threads per CTA (half row)  -- R6 scaffold
#define NO    4             // channel octs of 8: quadA=o, quadB=o+4
#define SW2   220           // window: 76 left halo + 128 + 16 right
#define HALO  76
#define DG    12            // disparities per split (d=11 computed by both)
#define TAPS  13            // DG + 1

__device__ __forceinline__ __half2 u2h2(unsigned u) {
    __half2 r; memcpy(&r, &u, 4); return r;
}

// out[b,d,h,w] = sum_c |feat_l[b,c,h,w] - (w0*fr[c,x0+d] + w1*fr[c,x0+d+1])|
// R6 scaffold exactly (1024 CTAs of 128 threads: 2 halves x 2 d-splits,
// in-loop feat_l loads, half2 accum / fp32 flush every 8 channels). Single
// change: feat_r window packed as 16B octs of 8 fp16 channels so the gather
// is 13 x LDS.128 per oct (52 instr/thread vs 104 LDS.64), ~25% fewer
// shared-crossbar wavefronts and half the gather issue slots.
// Oct o = channels (2o,2o+16 | 2o+1,2o+17 | 2o+8,2o+24 | 2o+9,2o+25).
__global__ __launch_bounds__(WT)
void cost_volume_kernel(const float* __restrict__ feat_l,
                        const float* __restrict__ feat_r,
                        const float* __restrict__ disp,
                        float* __restrict__ out)
{
    __shared__ __align__(16) uint4 s_o[NO][SW2];   // 14080 B

    const int xb    = blockIdx.x;        // 0..3 : (spl<<1)|half
    const int half_ = xb & 1;
    const int spl   = xb >> 1;
    const int h     = blockIdx.y;
    const int b     = blockIdx.z;
    const int tid   = threadIdx.x;
    const int W0    = half_ * WT;
    const int base  = W0 - HALO;         // global x of window index 0
    const int dlo   = spl * 11;          // 0 or 11

    // ---- stage zero-padded feat_r window as 8-channel octs ----
    {
        const float* fr0 = feat_r + (((long)b * C_) * H_ + h) * W_;
        #pragma unroll
        for (int s = 0; s < 2; s++) {
            const int i = tid + s * WT;
            if (i < SW2) {
                const int gx = base + i;
                const bool v = (gx >= 0) & (gx < W_);
                const int gxc = v ? gx : 0;
                #pragma unroll
                for (int o = 0; o < NO; o++) {
                    const float a0 = v ? __ldg(fr0 + (2*o)      * HW + gxc) : 0.0f;
                    const float a1 = v ? __ldg(fr0 + (2*o + 1)  * HW + gxc) : 0.0f;
                    const float a2 = v ? __ldg(fr0 + (2*o + 16) * HW + gxc) : 0.0f;
                    const float a3 = v ? __ldg(fr0 + (2*o + 17) * HW + gxc) : 0.0f;
                    const float b0 = v ? __ldg(fr0 + (2*o + 8)  * HW + gxc) : 0.0f;
                    const float b1 = v ? __ldg(fr0 + (2*o + 9)  * HW + gxc) : 0.0f;
                    const float b2 = v ? __ldg(fr0 + (2*o + 24) * HW + gxc) : 0.0f;
                    const float b3 = v ? __ldg(fr0 + (2*o + 25) * HW + gxc) : 0.0f;
                    __half2 px = __floats2half2_rn(a0, a2);
                    __half2 py = __floats2half2_rn(a1, a3);
                    __half2 pz = __floats2half2_rn(b0, b2);
                    __half2 pw = __floats2half2_rn(b1, b3);
                    uint4 ov;
                    memcpy(&ov.x, &px, 4); memcpy(&ov.y, &py, 4);
                    memcpy(&ov.z, &pz, 4); memcpy(&ov.w, &pw, 4);
                    s_o[o][i] = ov;       // STS.128, consecutive lanes -> conflict-free
                }
            }
        }
    }

    // ---- per-thread interpolation setup (overlaps fill) ----
    const int   w    = W0 + tid;
    const float dval = __ldg(disp + ((long)b * H_ + h) * W_ + w);
    const float px0  = ((float)w - dval) - (float)(MAXD - 1);
    const float xf   = floorf(px0);
    const float w1   = px0 - xf;          // right-neighbor weight (const over d)
    const float w0   = 1.0f - w1;
    int x0l = (int)xf - base;             // in [tid+1, tid+65]
    x0l = max(0, min(SW2 - 24, x0l));     // xs + TAPS <= 220 for both splits
    const int xs = x0l + dlo;

    const __half2 nw0 = __float2half2_rn(-w0);
    const __half2 nw1 = __float2half2_rn(-w1);

    __syncthreads();

    float accf[DG];
    #pragma unroll
    for (int d = 0; d < DG; d++) accf[d] = 0.0f;

    const float* fl0 = feat_l + (((long)b * C_) * H_ + h) * W_ + w;

    #pragma unroll 1
    for (int o = 0; o < NO; o++) {                 // 4 octs (8 channels each)
        // in-loop feat_l loads for this oct (spaced through mainloop)
        const float a0 = __ldg(fl0 + (2*o)      * HW);
        const float a1 = __ldg(fl0 + (2*o + 1)  * HW);
        const float a2 = __ldg(fl0 + (2*o + 16) * HW);
        const float a3 = __ldg(fl0 + (2*o + 17) * HW);
        const float b0 = __ldg(fl0 + (2*o + 8)  * HW);
        const float b1 = __ldg(fl0 + (2*o + 9)  * HW);
        const float b2 = __ldg(fl0 + (2*o + 24) * HW);
        const float b3 = __ldg(fl0 + (2*o + 25) * HW);
        const __half2 fX = __floats2half2_rn(a0, a2);
        const __half2 fY = __floats2half2_rn(a1, a3);
        const __half2 fZ = __floats2half2_rn(b0, b2);
        const __half2 fW = __floats2half2_rn(b1, b3);

        const uint4* row = &s_o[o][xs];
        uint4 t[TAPS];
        #pragma unroll
        for (int j = 0; j < TAPS; j++) t[j] = row[j];   // 13 x LDS.128

        __half2 acc2[DG];
        #pragma unroll
        for (int d = 0; d < DG; d++) acc2[d] = __float2half2_rn(0.0f);

        #pragma unroll
        for (int d = 0; d < DG; d++) {
            __half2 u0 = __hfma2(u2h2(t[d].x),     nw0, fX);
            u0         = __hfma2(u2h2(t[d + 1].x), nw1, u0);
            __half2 u1 = __hfma2(u2h2(t[d].y),     nw0, fY);
            u1         = __hfma2(u2h2(t[d + 1].y), nw1, u1);
            __half2 u2 = __hfma2(u2h2(t[d].z),     nw0, fZ);
            u2         = __hfma2(u2h2(t[d + 1].z), nw1, u2);
            __half2 u3 = __hfma2(u2h2(t[d].w),     nw0, fW);
            u3         = __hfma2(u2h2(t[d + 1].w), nw1, u3);
            __half2 s01 = __hadd2(__habs2(u0), __habs2(u1));
            __half2 s23 = __hadd2(__habs2(u2), __habs2(u3));
            acc2[d] = __hadd2(acc2[d], __hadd2(s01, s23));
        }

        // flush packed half accumulators to fp32 (every 8 channels, as R6)
        #pragma unroll
        for (int d = 0; d < DG; d++) {
            float2 f = __half22float2(acc2[d]);
            accf[d] += f.x + f.y;
        }
    }

    // ---- write out[b, dlo+d, h, w] (d=11 written by both splits, same value) ----
    float* orow = out + (((long)b * D_ + dlo) * H_ + h) * W_ + w;
    #pragma unroll
    for (int d = 0; d < DG; d++)
        orow[(long)d * HW] = accf[d];
}

extern "C" void kernel_launch(void* const* d_in, const int* in_sizes, int n_in,
                              void* d_out, int out_size)
{
    (void)in_sizes; (void)n_in; (void)out_size;
    const float* feat_l = (const float*)d_in[0];
    const float* feat_r = (const float*)d_in[1];
    const float* disp   = (const float*)d_in[2];
    float* out = (float*)d_out;

    dim3 grid(4, H_, B_);     // 2 halves x 2 d-splits = 1024 CTAs (R6 scaffold)
    cost_volume_kernel<<<grid, WT>>>(feat_l, feat_r, disp, out);
}